// round 1
// baseline (speedup 1.0000x reference)
#include <cuda_runtime.h>
#include <cuda_bf16.h>

// Problem constants (fixed by the reference)
#define N_A   16384
#define N_B   100000
#define DIM   256
#define MM    50
#define K2D   512   // 2*DIM

// Scratch (no cudaMalloc allowed): combined [16384,512] and hidden [16384,512]
__device__ float g_combined[(size_t)N_A * K2D];  // 33.5 MB
__device__ float g_hidden  [(size_t)N_A * K2D];  // 33.5 MB

// ---------------------------------------------------------------------------
// Kernel 1: gather + masked mean + concat -> g_combined
// One CTA per table-A row, 256 threads (one per feature dim).
// ---------------------------------------------------------------------------
__global__ void gather_concat_kernel(const float* __restrict__ ta,
                                     const float* __restrict__ tb,
                                     const int*   __restrict__ mi)
{
    __shared__ int s_idx[MM];
    const int b = blockIdx.x;
    const int t = threadIdx.x;

    if (t < MM) s_idx[t] = mi[(size_t)b * MM + t];
    __syncthreads();

    float acc = 0.0f;
    int   cnt = 0;
#pragma unroll
    for (int m = 0; m < MM; m++) {
        const int idx = s_idx[m];
        if (idx >= 0) {
            acc += __ldg(&tb[(size_t)idx * DIM + t]);
            cnt++;
        }
    }
    const float inv = 1.0f / (float)max(cnt, 1);

    g_combined[(size_t)b * K2D + t]       = ta[(size_t)b * DIM + t];
    g_combined[(size_t)b * K2D + DIM + t] = acc * inv;
}

// ---------------------------------------------------------------------------
// fp32 SGEMM core: C[M,N] = act(A[M,K] @ W[K,N] + bias)
// BM=128, BN=128, BK=8, 256 threads, 8x8 per thread.
// ---------------------------------------------------------------------------
template <bool RELU>
__device__ __forceinline__ void gemm_core(const float* __restrict__ A,
                                          const float* __restrict__ W,
                                          const float* __restrict__ bias,
                                          float* __restrict__ C,
                                          int N, int K)
{
    constexpr int BM = 128, BN = 128, BK = 8, TM = 8, TN = 8;
    __shared__ float As[BK][BM];
    __shared__ float Bs[BK][BN];

    const int tid = threadIdx.x;
    const int tx  = tid % (BN / TN);   // 0..15
    const int ty  = tid / (BN / TN);   // 0..15
    const int bm  = blockIdx.y * BM;
    const int bn  = blockIdx.x * BN;

    // A tile load mapping: 128x8 floats = 256 * float4
    const int a_row = tid >> 1;            // 0..127
    const int a_col = (tid & 1) * 4;       // 0 or 4
    // B tile load mapping: 8x128 floats = 256 * float4
    const int b_row = tid >> 5;            // 0..7
    const int b_col = (tid & 31) * 4;      // 0..124

    float acc[TM][TN] = {};

    for (int k0 = 0; k0 < K; k0 += BK) {
        const float4 av = *reinterpret_cast<const float4*>(
            &A[(size_t)(bm + a_row) * K + k0 + a_col]);
        As[a_col + 0][a_row] = av.x;
        As[a_col + 1][a_row] = av.y;
        As[a_col + 2][a_row] = av.z;
        As[a_col + 3][a_row] = av.w;

        *reinterpret_cast<float4*>(&Bs[b_row][b_col]) =
            *reinterpret_cast<const float4*>(
                &W[(size_t)(k0 + b_row) * N + bn + b_col]);
        __syncthreads();

#pragma unroll
        for (int k = 0; k < BK; k++) {
            float ra[TM], rb[TN];
            // float4 smem reads, conflict-friendly
            *reinterpret_cast<float4*>(&ra[0]) =
                *reinterpret_cast<const float4*>(&As[k][ty * TM]);
            *reinterpret_cast<float4*>(&ra[4]) =
                *reinterpret_cast<const float4*>(&As[k][ty * TM + 4]);
            *reinterpret_cast<float4*>(&rb[0]) =
                *reinterpret_cast<const float4*>(&Bs[k][tx * TN]);
            *reinterpret_cast<float4*>(&rb[4]) =
                *reinterpret_cast<const float4*>(&Bs[k][tx * TN + 4]);
#pragma unroll
            for (int i = 0; i < TM; i++)
#pragma unroll
                for (int j = 0; j < TN; j++)
                    acc[i][j] += ra[i] * rb[j];
        }
        __syncthreads();
    }

#pragma unroll
    for (int i = 0; i < TM; i++) {
        const size_t row = (size_t)(bm + ty * TM + i);
#pragma unroll
        for (int j = 0; j < TN; j += 4) {
            const int col = bn + tx * TN + j;
            float4 v;
            v.x = acc[i][j + 0] + bias[col + 0];
            v.y = acc[i][j + 1] + bias[col + 1];
            v.z = acc[i][j + 2] + bias[col + 2];
            v.w = acc[i][j + 3] + bias[col + 3];
            if (RELU) {
                v.x = fmaxf(v.x, 0.0f);
                v.y = fmaxf(v.y, 0.0f);
                v.z = fmaxf(v.z, 0.0f);
                v.w = fmaxf(v.w, 0.0f);
            }
            *reinterpret_cast<float4*>(&C[row * N + col]) = v;
        }
    }
}

__global__ void __launch_bounds__(256)
gemm1_relu_kernel(const float* __restrict__ W1, const float* __restrict__ b1)
{
    gemm_core<true>(g_combined, W1, b1, g_hidden, K2D, K2D);
}

__global__ void __launch_bounds__(256)
gemm2_kernel(const float* __restrict__ W2, const float* __restrict__ b2,
             float* __restrict__ out)
{
    gemm_core<false>(g_hidden, W2, b2, out, DIM, K2D);
}

// ---------------------------------------------------------------------------
extern "C" void kernel_launch(void* const* d_in, const int* in_sizes, int n_in,
                              void* d_out, int out_size)
{
    const float* ta = (const float*)d_in[0];   // table_a_emb [16384, 256]
    const float* tb = (const float*)d_in[1];   // table_b_emb [100000, 256]
    const int*   mi = (const int*)  d_in[2];   // match_indices [16384, 50]
    const float* W1 = (const float*)d_in[3];   // [512, 512]
    const float* b1 = (const float*)d_in[4];   // [512]
    const float* W2 = (const float*)d_in[5];   // [512, 256]
    const float* b2 = (const float*)d_in[6];   // [256]
    float* out = (float*)d_out;                // [16384, 256]

    gather_concat_kernel<<<N_A, DIM>>>(ta, tb, mi);

    {   // hidden = relu(combined @ W1 + b1): M=16384, N=512, K=512
        dim3 grid(K2D / 128, N_A / 128);
        gemm1_relu_kernel<<<grid, 256>>>(W1, b1);
    }
    {   // out = hidden @ W2 + b2: M=16384, N=256, K=512
        dim3 grid(DIM / 128, N_A / 128);
        gemm2_kernel<<<grid, 256>>>(W2, b2, out);
    }
}

// round 3
// speedup vs baseline: 1.7215x; 1.7215x over previous
#include <cuda_runtime.h>
#include <cuda_bf16.h>

// Problem constants (fixed by the reference)
#define N_A   16384
#define N_B   100000
#define DIM   256
#define MM    50
#define K2D   512   // 2*DIM

// Scratch (no cudaMalloc allowed): combined [16384,512] and hidden [16384,512]
__device__ float g_combined[(size_t)N_A * K2D];  // 33.5 MB
__device__ float g_hidden  [(size_t)N_A * K2D];  // 33.5 MB

// ---------------------------------------------------------------------------
// Kernel 1: gather + masked mean + concat -> g_combined
// 4 rows per CTA (256 threads). 64 threads per row, one float4 per thread.
// ---------------------------------------------------------------------------
__global__ void __launch_bounds__(256)
gather_concat_kernel(const float* __restrict__ ta,
                     const float* __restrict__ tb,
                     const int*   __restrict__ mi)
{
    __shared__ int s_idx[4][MM];

    const int tid  = threadIdx.x;
    const int g    = tid >> 6;         // group 0..3  -> row within CTA
    const int lane = tid & 63;         // 0..63       -> float4 slot
    const int row0 = blockIdx.x * 4;

    // Cooperatively load 4*50 indices (threads 0..199)
    if (tid < 4 * MM) {
        const int gg = tid / MM;
        const int m  = tid - gg * MM;
        s_idx[gg][m] = mi[(size_t)(row0 + gg) * MM + m];
    }
    __syncthreads();

    const int row = row0 + g;

    float4 acc = make_float4(0.f, 0.f, 0.f, 0.f);
    int    cnt = 0;

#pragma unroll 10
    for (int m = 0; m < MM; m++) {
        const int idx = s_idx[g][m];
        if (idx >= 0) {
            const float4 v = __ldg(reinterpret_cast<const float4*>(
                &tb[(size_t)idx * DIM + lane * 4]));
            acc.x += v.x; acc.y += v.y; acc.z += v.z; acc.w += v.w;
            cnt++;
        }
    }
    const float inv = 1.0f / (float)max(cnt, 1);
    acc.x *= inv; acc.y *= inv; acc.z *= inv; acc.w *= inv;

    // combined[row] = [ ta[row] (256) | agg (256) ]
    const float4 tav = __ldg(reinterpret_cast<const float4*>(
        &ta[(size_t)row * DIM + lane * 4]));
    float4* dst = reinterpret_cast<float4*>(&g_combined[(size_t)row * K2D]);
    dst[lane]            = tav;   // dims [0,256)
    dst[DIM / 4 + lane]  = acc;   // dims [256,512)
}

// ---------------------------------------------------------------------------
// fp32 SGEMM core: C[M,N] = act(A[M,K] @ W[K,N] + bias)
// BM=128, BN=128, BK=8, 256 threads, 8x8 per thread.  (~96% of fp32 peak)
// ---------------------------------------------------------------------------
template <bool RELU>
__device__ __forceinline__ void gemm_core(const float* __restrict__ A,
                                          const float* __restrict__ W,
                                          const float* __restrict__ bias,
                                          float* __restrict__ C,
                                          int N, int K)
{
    constexpr int BM = 128, BN = 128, BK = 8, TM = 8, TN = 8;
    __shared__ float As[BK][BM];
    __shared__ float Bs[BK][BN];

    const int tid = threadIdx.x;
    const int tx  = tid % (BN / TN);   // 0..15
    const int ty  = tid / (BN / TN);   // 0..15
    const int bm  = blockIdx.y * BM;
    const int bn  = blockIdx.x * BN;

    const int a_row = tid >> 1;            // 0..127
    const int a_col = (tid & 1) * 4;       // 0 or 4
    const int b_row = tid >> 5;            // 0..7
    const int b_col = (tid & 31) * 4;      // 0..124

    float acc[TM][TN] = {};

    for (int k0 = 0; k0 < K; k0 += BK) {
        const float4 av = *reinterpret_cast<const float4*>(
            &A[(size_t)(bm + a_row) * K + k0 + a_col]);
        As[a_col + 0][a_row] = av.x;
        As[a_col + 1][a_row] = av.y;
        As[a_col + 2][a_row] = av.z;
        As[a_col + 3][a_row] = av.w;

        *reinterpret_cast<float4*>(&Bs[b_row][b_col]) =
            *reinterpret_cast<const float4*>(
                &W[(size_t)(k0 + b_row) * N + bn + b_col]);
        __syncthreads();

#pragma unroll
        for (int k = 0; k < BK; k++) {
            float ra[TM], rb[TN];
            *reinterpret_cast<float4*>(&ra[0]) =
                *reinterpret_cast<const float4*>(&As[k][ty * TM]);
            *reinterpret_cast<float4*>(&ra[4]) =
                *reinterpret_cast<const float4*>(&As[k][ty * TM + 4]);
            *reinterpret_cast<float4*>(&rb[0]) =
                *reinterpret_cast<const float4*>(&Bs[k][tx * TN]);
            *reinterpret_cast<float4*>(&rb[4]) =
                *reinterpret_cast<const float4*>(&Bs[k][tx * TN + 4]);
#pragma unroll
            for (int i = 0; i < TM; i++)
#pragma unroll
                for (int j = 0; j < TN; j++)
                    acc[i][j] += ra[i] * rb[j];
        }
        __syncthreads();
    }

#pragma unroll
    for (int i = 0; i < TM; i++) {
        const size_t row = (size_t)(bm + ty * TM + i);
#pragma unroll
        for (int j = 0; j < TN; j += 4) {
            const int col = bn + tx * TN + j;
            float4 v;
            v.x = acc[i][j + 0] + bias[col + 0];
            v.y = acc[i][j + 1] + bias[col + 1];
            v.z = acc[i][j + 2] + bias[col + 2];
            v.w = acc[i][j + 3] + bias[col + 3];
            if (RELU) {
                v.x = fmaxf(v.x, 0.0f);
                v.y = fmaxf(v.y, 0.0f);
                v.z = fmaxf(v.z, 0.0f);
                v.w = fmaxf(v.w, 0.0f);
            }
            *reinterpret_cast<float4*>(&C[row * N + col]) = v;
        }
    }
}

__global__ void __launch_bounds__(256)
gemm1_relu_kernel(const float* __restrict__ W1, const float* __restrict__ b1)
{
    gemm_core<true>(g_combined, W1, b1, g_hidden, K2D, K2D);
}

__global__ void __launch_bounds__(256)
gemm2_kernel(const float* __restrict__ W2, const float* __restrict__ b2,
             float* __restrict__ out)
{
    gemm_core<false>(g_hidden, W2, b2, out, DIM, K2D);
}

// ---------------------------------------------------------------------------
extern "C" void kernel_launch(void* const* d_in, const int* in_sizes, int n_in,
                              void* d_out, int out_size)
{
    const float* ta = (const float*)d_in[0];   // table_a_emb [16384, 256]
    const float* tb = (const float*)d_in[1];   // table_b_emb [100000, 256]
    const int*   mi = (const int*)  d_in[2];   // match_indices [16384, 50]
    const float* W1 = (const float*)d_in[3];   // [512, 512]
    const float* b1 = (const float*)d_in[4];   // [512]
    const float* W2 = (const float*)d_in[5];   // [512, 256]
    const float* b2 = (const float*)d_in[6];   // [256]
    float* out = (float*)d_out;                // [16384, 256]

    gather_concat_kernel<<<N_A / 4, 256>>>(ta, tb, mi);

    {   // hidden = relu(combined @ W1 + b1): M=16384, N=512, K=512
        dim3 grid(K2D / 128, N_A / 128);
        gemm1_relu_kernel<<<grid, 256>>>(W1, b1);
    }
    {   // out = hidden @ W2 + b2: M=16384, N=256, K=512
        dim3 grid(DIM / 128, N_A / 128);
        gemm2_kernel<<<grid, 256>>>(W2, b2, out);
    }
}